// round 1
// baseline (speedup 1.0000x reference)
#include <cuda_runtime.h>

#define NQ    4
#define CIN   64
#define HH    64
#define WW    64
#define OUTC  128
#define TH    8
#define TW    16
#define NTHR  128
#define HALO_H (TH + 2)
#define HALO_W (TW + 2)
#define HALO_N (HALO_H * HALO_W)   // 180

// Fixed gate matrices: [0..31] = U3 per wire (4 x 8 floats), [32..63] = CU3 per wire.
// Each 2x2 complex matrix stored as (m00r,m00i,m01r,m01i,m10r,m10i,m11r,m11i).
__device__ float g_gates[64];

__global__ void init_gates_kernel(const float* __restrict__ u3p,
                                  const float* __restrict__ cu3p)
{
    int i = threadIdx.x;
    if (i < 8) {
        const float* p = (i < 4) ? (u3p + i * 3) : (cu3p + (i - 4) * 3);
        float th = p[0], ph = p[1], la = p[2];
        float st, ct;   sincosf(0.5f * th, &st, &ct);
        float sl, cl;   sincosf(la, &sl, &cl);
        float sp, cp;   sincosf(ph, &sp, &cp);
        float spl, cpl; sincosf(ph + la, &spl, &cpl);
        float* o = g_gates + i * 8;
        o[0] = ct;        o[1] = 0.f;        // U00 = cos(th/2)
        o[2] = -cl * st;  o[3] = -sl * st;   // U01 = -e^{i la} sin
        o[4] = cp * st;   o[5] = sp * st;    // U10 =  e^{i ph} sin
        o[6] = cpl * ct;  o[7] = spl * ct;   // U11 =  e^{i(ph+la)} cos
    }
}

__global__ __launch_bounds__(NTHR, 4)
void qconv_kernel(const float* __restrict__ x,     // (16,64,64,64)
                  const float* __restrict__ fc1w,  // (4,576)
                  const float* __restrict__ fc1b,  // (4,)
                  const float* __restrict__ fcw,   // (128,4)
                  const float* __restrict__ fcb,   // (128,)
                  float* __restrict__ out)         // (16,4096,128) flat
{
    __shared__ float4 wq[CIN * 9];      // [c*9+tap] -> weights for the 4 angles
    __shared__ float  xs[2][HALO_N];    // double-buffered halo tile (one channel)
    __shared__ float4 ez[NTHR];         // per-pixel <Z> expectations

    const int t  = threadIdx.x;
    const int b  = blockIdx.z;
    const int h0 = blockIdx.y * TH;
    const int w0 = blockIdx.x * TW;

    // Stage conv weights into smem, transposed to float4 across the 4 outputs.
    for (int f = t; f < CIN * 9; f += NTHR)
        wq[f] = make_float4(fc1w[f], fc1w[576 + f], fc1w[1152 + f], fc1w[1728 + f]);

    const int ty = t >> 4;   // 0..7
    const int tx = t & 15;   // 0..15

    const float* xb0 = x + ((size_t)b * CIN) * (HH * WW);
    const int by = h0 - 1, bx = w0 - 1;

    // Per-thread staging coordinates (each thread loads up to 2 halo elements).
    const int s_r0 = t / HALO_W, s_c0 = t - s_r0 * HALO_W;
    const int idx1 = t + NTHR;
    const int s_r1 = idx1 / HALO_W, s_c1 = idx1 - s_r1 * HALO_W;
    const bool has1 = (idx1 < HALO_N);

    // Stage channel 0 into buffer 0.
    {
        int gy = by + s_r0, gx = bx + s_c0;
        float v = 0.f;
        if ((unsigned)gy < (unsigned)HH && (unsigned)gx < (unsigned)WW)
            v = xb0[gy * WW + gx];
        xs[0][t] = v;
        if (has1) {
            gy = by + s_r1; gx = bx + s_c1;
            v = 0.f;
            if ((unsigned)gy < (unsigned)HH && (unsigned)gx < (unsigned)WW)
                v = xb0[gy * WW + gx];
            xs[0][idx1] = v;
        }
    }
    __syncthreads();

    float a0 = fc1b[0], a1 = fc1b[1], a2 = fc1b[2], a3 = fc1b[3];

    for (int c = 0; c < CIN; ++c) {
        // Prefetch next channel into registers (latency overlaps compute).
        float p0 = 0.f, p1 = 0.f;
        if (c + 1 < CIN) {
            const float* xc = xb0 + (size_t)(c + 1) * (HH * WW);
            int gy = by + s_r0, gx = bx + s_c0;
            if ((unsigned)gy < (unsigned)HH && (unsigned)gx < (unsigned)WW)
                p0 = xc[gy * WW + gx];
            if (has1) {
                gy = by + s_r1; gx = bx + s_c1;
                if ((unsigned)gy < (unsigned)HH && (unsigned)gx < (unsigned)WW)
                    p1 = xc[gy * WW + gx];
            }
        }

        const float*  xsc = xs[c & 1];
        const float4* wp  = wq + c * 9;
        #pragma unroll
        for (int di = 0; di < 3; ++di) {
            #pragma unroll
            for (int dj = 0; dj < 3; ++dj) {
                float  v = xsc[(ty + di) * HALO_W + tx + dj];
                float4 w = wp[di * 3 + dj];
                a0 = fmaf(v, w.x, a0);
                a1 = fmaf(v, w.y, a1);
                a2 = fmaf(v, w.z, a2);
                a3 = fmaf(v, w.w, a3);
            }
        }

        if (c + 1 < CIN) {
            float* d = xs[(c + 1) & 1];
            d[t] = p0;
            if (has1) d[idx1] = p1;
        }
        __syncthreads();
    }

    // ---------------- quantum circuit (per pixel, in registers) ----------------
    // Single-qubit states after RY(ang) then fixed U3: S[q] = (ar, ai, br, bi)
    float S[NQ][4];
    float angs[NQ] = {a0, a1, a2, a3};
    #pragma unroll
    for (int q = 0; q < NQ; ++q) {
        float st, ct;
        sincosf(0.5f * angs[q], &st, &ct);
        const float* m = g_gates + q * 8;
        S[q][0] = m[0] * ct + m[2] * st;
        S[q][1] = m[1] * ct + m[3] * st;
        S[q][2] = m[4] * ct + m[6] * st;
        S[q][3] = m[5] * ct + m[7] * st;
    }

    // Product state psi[i], i = b0*8 + b1*4 + b2*2 + b3 (wire 0 = MSB).
    float q01r[4], q01i[4], q23r[4], q23i[4];
    #pragma unroll
    for (int i0 = 0; i0 < 2; ++i0)
        #pragma unroll
        for (int i1 = 0; i1 < 2; ++i1) {
            float xr = S[0][i0 * 2], xi = S[0][i0 * 2 + 1];
            float yr = S[1][i1 * 2], yi = S[1][i1 * 2 + 1];
            q01r[i0 * 2 + i1] = xr * yr - xi * yi;
            q01i[i0 * 2 + i1] = xr * yi + xi * yr;
            xr = S[2][i0 * 2]; xi = S[2][i0 * 2 + 1];
            yr = S[3][i1 * 2]; yi = S[3][i1 * 2 + 1];
            q23r[i0 * 2 + i1] = xr * yr - xi * yi;
            q23i[i0 * 2 + i1] = xr * yi + xi * yr;
        }

    float pr[16], pi[16];
    #pragma unroll
    for (int u = 0; u < 4; ++u)
        #pragma unroll
        for (int v = 0; v < 4; ++v) {
            pr[u * 4 + v] = q01r[u] * q23r[v] - q01i[u] * q23i[v];
            pi[u * 4 + v] = q01r[u] * q23i[v] + q01i[u] * q23r[v];
        }

    // CU3 ring: gate g has control g, target (g+1)%4. Bit mask for wire w: 8>>w.
    #pragma unroll
    for (int g = 0; g < 4; ++g) {
        const float* U = g_gates + 32 + g * 8;
        float u00r = U[0], u00i = U[1], u01r = U[2], u01i = U[3];
        float u10r = U[4], u10i = U[5], u11r = U[6], u11i = U[7];
        const int bc = 8 >> g;
        const int bt = 8 >> ((g + 1) & 3);
        #pragma unroll
        for (int i = 0; i < 16; ++i) {
            if ((i & bc) && !(i & bt)) {
                const int j = i | bt;
                float x0r = pr[i], x0i = pi[i], x1r = pr[j], x1i = pi[j];
                pr[i] = u00r * x0r - u00i * x0i + u01r * x1r - u01i * x1i;
                pi[i] = u00r * x0i + u00i * x0r + u01r * x1i + u01i * x1r;
                pr[j] = u10r * x0r - u10i * x0i + u11r * x1r - u11i * x1i;
                pi[j] = u10r * x0i + u10i * x0r + u11r * x1i + u11i * x1r;
            }
        }
    }

    // <Z> on each wire.
    float e0 = 0.f, e1 = 0.f, e2 = 0.f, e3 = 0.f;
    #pragma unroll
    for (int i = 0; i < 16; ++i) {
        float pp = pr[i] * pr[i] + pi[i] * pi[i];
        e0 += (i & 8) ? -pp : pp;
        e1 += (i & 4) ? -pp : pp;
        e2 += (i & 2) ? -pp : pp;
        e3 += (i & 1) ? -pp : pp;
    }

    ez[t] = make_float4(e0, e1, e2, e3);
    __syncthreads();

    // ---------------- coalesced FC epilogue ----------------
    // Each warp handles 32 pixels; lane k owns output channels 4k..4k+3, so a
    // warp's STG.128s for one pixel form one contiguous 512B burst.
    const int lane = t & 31;
    const int wi   = t >> 5;
    const float4* fw4 = (const float4*)fcw;   // row oc -> float4 index oc
    float4 wr0 = fw4[4 * lane + 0];
    float4 wr1 = fw4[4 * lane + 1];
    float4 wr2 = fw4[4 * lane + 2];
    float4 wr3 = fw4[4 * lane + 3];
    float4 bb4 = ((const float4*)fcb)[lane];

    float4* ob = (float4*)out + (size_t)b * 4096 * 32;
    #pragma unroll 4
    for (int j = 0; j < 32; ++j) {
        const int lp = wi * 32 + j;
        float4 e = ez[lp];
        const int py = h0 + (lp >> 4);
        const int px = w0 + (lp & 15);
        const int p  = py * WW + px;
        float4 o;
        o.x = bb4.x + wr0.x * e.x + wr0.y * e.y + wr0.z * e.z + wr0.w * e.w;
        o.y = bb4.y + wr1.x * e.x + wr1.y * e.y + wr1.z * e.z + wr1.w * e.w;
        o.z = bb4.z + wr2.x * e.x + wr2.y * e.y + wr2.z * e.z + wr2.w * e.w;
        o.w = bb4.w + wr3.x * e.x + wr3.y * e.y + wr3.z * e.z + wr3.w * e.w;
        ob[(size_t)p * 32 + lane] = o;
    }
}

extern "C" void kernel_launch(void* const* d_in, const int* in_sizes, int n_in,
                              void* d_out, int out_size)
{
    (void)in_sizes; (void)n_in; (void)out_size;
    const float* x    = (const float*)d_in[0];
    const float* fc1w = (const float*)d_in[1];
    const float* fc1b = (const float*)d_in[2];
    const float* u3p  = (const float*)d_in[3];
    const float* cu3p = (const float*)d_in[4];
    const float* fcw  = (const float*)d_in[5];
    const float* fcb  = (const float*)d_in[6];
    float* out = (float*)d_out;

    init_gates_kernel<<<1, 32>>>(u3p, cu3p);
    dim3 grid(WW / TW, HH / TH, 16);
    qconv_kernel<<<grid, NTHR>>>(x, fc1w, fc1b, fcw, fcb, out);
}

// round 2
// speedup vs baseline: 1.4072x; 1.4072x over previous
#include <cuda_runtime.h>

#define NQ    4
#define CIN   64
#define HH    64
#define WW    64
#define OUTC  128
#define TH    8
#define TW    16
#define NTHR  128
#define HALO_H (TH + 2)
#define HALO_W (TW + 2)
#define HALO_N (HALO_H * HALO_W)   // 180

// Fixed gate matrices: [0..31] = U3 per wire, [32..63] = CU3 per wire.
// Each 2x2 complex matrix stored as (m00r,m00i,m01r,m01i,m10r,m10i,m11r,m11i).
__device__ float g_gates[64];

__global__ void init_gates_kernel(const float* __restrict__ u3p,
                                  const float* __restrict__ cu3p)
{
    int i = threadIdx.x;
    if (i < 8) {
        const float* p = (i < 4) ? (u3p + i * 3) : (cu3p + (i - 4) * 3);
        float th = p[0], ph = p[1], la = p[2];
        float st, ct;   sincosf(0.5f * th, &st, &ct);
        float sl, cl;   sincosf(la, &sl, &cl);
        float sp, cp;   sincosf(ph, &sp, &cp);
        float spl, cpl; sincosf(ph + la, &spl, &cpl);
        float* o = g_gates + i * 8;
        o[0] = ct;        o[1] = 0.f;
        o[2] = -cl * st;  o[3] = -sl * st;
        o[4] = cp * st;   o[5] = sp * st;
        o[6] = cpl * ct;  o[7] = spl * ct;
    }
}

__global__ __launch_bounds__(NTHR, 4)
void qconv_kernel(const float* __restrict__ x,     // (16,64,64,64)
                  const float* __restrict__ fc1w,  // (4,576)
                  const float* __restrict__ fc1b,  // (4,)
                  const float* __restrict__ fcw,   // (128,4)
                  const float* __restrict__ fcb,   // (128,)
                  float* __restrict__ out)         // (16,4096,128) flat
{
    __shared__ float4 wq[CIN * 9];        // [c*9+tap] -> weights over the 4 angles
    __shared__ float4 xs4[2][2][HALO_N];  // [buf][chan-group][pos] 4 channels/float4
    __shared__ float4 ez[NTHR];

    const int t  = threadIdx.x;
    const int b  = blockIdx.z;
    const int h0 = blockIdx.y * TH;
    const int w0 = blockIdx.x * TW;

    for (int f = t; f < CIN * 9; f += NTHR)
        wq[f] = make_float4(fc1w[f], fc1w[576 + f], fc1w[1152 + f], fc1w[1728 + f]);

    const int ty = t >> 4;   // 0..7
    const int tx = t & 15;   // 0..15
    const int by = h0 - 1, bx = w0 - 1;

    // Channel-invariant halo staging: predicate + clamped base, computed ONCE.
    const int s_r0 = t / HALO_W, s_c0 = t - s_r0 * HALO_W;
    const int idx1 = t + NTHR;
    const int s_r1 = idx1 / HALO_W, s_c1 = idx1 - s_r1 * HALO_W;
    const bool has1 = (idx1 < HALO_N);

    int gy0 = by + s_r0, gx0 = bx + s_c0;
    const bool valid0 = (unsigned)gy0 < (unsigned)HH && (unsigned)gx0 < (unsigned)WW;
    int gy1 = by + s_r1, gx1 = bx + s_c1;
    const bool valid1 = has1 && (unsigned)gy1 < (unsigned)HH && (unsigned)gx1 < (unsigned)WW;

    const float* xb0 = x + ((size_t)b * CIN) * (HH * WW);
    const float* cur0 = xb0 + (valid0 ? gy0 * WW + gx0 : 0);
    const float* cur1 = xb0 + (valid1 ? gy1 * WW + gx1 : 0);

    float v0[8], v1[8];
    // ---- prologue: stage 0 (channels 0..7) ----
    #pragma unroll
    for (int k = 0; k < 8; ++k) v0[k] = valid0 ? cur0[k * (HH * WW)] : 0.f;
    #pragma unroll
    for (int k = 0; k < 8; ++k) v1[k] = valid1 ? cur1[k * (HH * WW)] : 0.f;
    cur0 += 8 * HH * WW; cur1 += 8 * HH * WW;

    xs4[0][0][t] = make_float4(v0[0], v0[1], v0[2], v0[3]);
    xs4[0][1][t] = make_float4(v0[4], v0[5], v0[6], v0[7]);
    if (has1) {
        xs4[0][0][idx1] = make_float4(v1[0], v1[1], v1[2], v1[3]);
        xs4[0][1][idx1] = make_float4(v1[4], v1[5], v1[6], v1[7]);
    }
    __syncthreads();

    float a0 = fc1b[0], a1 = fc1b[1], a2 = fc1b[2], a3 = fc1b[3];

    for (int s = 0; s < 8; ++s) {
        // Prefetch next 8 channels into registers (batched, MLP=16).
        if (s < 7) {
            #pragma unroll
            for (int k = 0; k < 8; ++k) v0[k] = valid0 ? cur0[k * (HH * WW)] : 0.f;
            #pragma unroll
            for (int k = 0; k < 8; ++k) v1[k] = valid1 ? cur1[k * (HH * WW)] : 0.f;
            cur0 += 8 * HH * WW; cur1 += 8 * HH * WW;
        }

        const float4* xg0 = xs4[s & 1][0];
        const float4* xg1 = xs4[s & 1][1];
        const float4* wp  = wq + s * 72;    // 8 channels x 9 taps

        #pragma unroll
        for (int di = 0; di < 3; ++di) {
            #pragma unroll
            for (int dj = 0; dj < 3; ++dj) {
                const int pos = (ty + di) * HALO_W + tx + dj;
                const int tap = di * 3 + dj;
                float4 xa = xg0[pos];
                float4 w;
                w = wp[0 * 9 + tap];
                a0 = fmaf(xa.x, w.x, a0); a1 = fmaf(xa.x, w.y, a1);
                a2 = fmaf(xa.x, w.z, a2); a3 = fmaf(xa.x, w.w, a3);
                w = wp[1 * 9 + tap];
                a0 = fmaf(xa.y, w.x, a0); a1 = fmaf(xa.y, w.y, a1);
                a2 = fmaf(xa.y, w.z, a2); a3 = fmaf(xa.y, w.w, a3);
                w = wp[2 * 9 + tap];
                a0 = fmaf(xa.z, w.x, a0); a1 = fmaf(xa.z, w.y, a1);
                a2 = fmaf(xa.z, w.z, a2); a3 = fmaf(xa.z, w.w, a3);
                w = wp[3 * 9 + tap];
                a0 = fmaf(xa.w, w.x, a0); a1 = fmaf(xa.w, w.y, a1);
                a2 = fmaf(xa.w, w.z, a2); a3 = fmaf(xa.w, w.w, a3);
                float4 xb4 = xg1[pos];
                w = wp[4 * 9 + tap];
                a0 = fmaf(xb4.x, w.x, a0); a1 = fmaf(xb4.x, w.y, a1);
                a2 = fmaf(xb4.x, w.z, a2); a3 = fmaf(xb4.x, w.w, a3);
                w = wp[5 * 9 + tap];
                a0 = fmaf(xb4.y, w.x, a0); a1 = fmaf(xb4.y, w.y, a1);
                a2 = fmaf(xb4.y, w.z, a2); a3 = fmaf(xb4.y, w.w, a3);
                w = wp[6 * 9 + tap];
                a0 = fmaf(xb4.z, w.x, a0); a1 = fmaf(xb4.z, w.y, a1);
                a2 = fmaf(xb4.z, w.z, a2); a3 = fmaf(xb4.z, w.w, a3);
                w = wp[7 * 9 + tap];
                a0 = fmaf(xb4.w, w.x, a0); a1 = fmaf(xb4.w, w.y, a1);
                a2 = fmaf(xb4.w, w.z, a2); a3 = fmaf(xb4.w, w.w, a3);
            }
        }
        __syncthreads();
        if (s < 7) {
            float4* d0 = xs4[(s + 1) & 1][0];
            float4* d1 = xs4[(s + 1) & 1][1];
            d0[t] = make_float4(v0[0], v0[1], v0[2], v0[3]);
            d1[t] = make_float4(v0[4], v0[5], v0[6], v0[7]);
            if (has1) {
                d0[idx1] = make_float4(v1[0], v1[1], v1[2], v1[3]);
                d1[idx1] = make_float4(v1[4], v1[5], v1[6], v1[7]);
            }
            __syncthreads();
        }
    }

    // ---------------- quantum circuit (per pixel, in registers) ----------------
    float S[NQ][4];
    float angs[NQ] = {a0, a1, a2, a3};
    #pragma unroll
    for (int q = 0; q < NQ; ++q) {
        float st, ct;
        __sincosf(0.5f * angs[q], &st, &ct);
        const float* m = g_gates + q * 8;
        S[q][0] = m[0] * ct + m[2] * st;
        S[q][1] = m[1] * ct + m[3] * st;
        S[q][2] = m[4] * ct + m[6] * st;
        S[q][3] = m[5] * ct + m[7] * st;
    }

    float q01r[4], q01i[4], q23r[4], q23i[4];
    #pragma unroll
    for (int i0 = 0; i0 < 2; ++i0)
        #pragma unroll
        for (int i1 = 0; i1 < 2; ++i1) {
            float xr = S[0][i0 * 2], xi = S[0][i0 * 2 + 1];
            float yr = S[1][i1 * 2], yi = S[1][i1 * 2 + 1];
            q01r[i0 * 2 + i1] = xr * yr - xi * yi;
            q01i[i0 * 2 + i1] = xr * yi + xi * yr;
            xr = S[2][i0 * 2]; xi = S[2][i0 * 2 + 1];
            yr = S[3][i1 * 2]; yi = S[3][i1 * 2 + 1];
            q23r[i0 * 2 + i1] = xr * yr - xi * yi;
            q23i[i0 * 2 + i1] = xr * yi + xi * yr;
        }

    float pr[16], pi[16];
    #pragma unroll
    for (int u = 0; u < 4; ++u)
        #pragma unroll
        for (int v = 0; v < 4; ++v) {
            pr[u * 4 + v] = q01r[u] * q23r[v] - q01i[u] * q23i[v];
            pi[u * 4 + v] = q01r[u] * q23i[v] + q01i[u] * q23r[v];
        }

    #pragma unroll
    for (int g = 0; g < 4; ++g) {
        const float* U = g_gates + 32 + g * 8;
        float u00r = U[0], u00i = U[1], u01r = U[2], u01i = U[3];
        float u10r = U[4], u10i = U[5], u11r = U[6], u11i = U[7];
        const int bc = 8 >> g;
        const int bt = 8 >> ((g + 1) & 3);
        #pragma unroll
        for (int i = 0; i < 16; ++i) {
            if ((i & bc) && !(i & bt)) {
                const int j = i | bt;
                float x0r = pr[i], x0i = pi[i], x1r = pr[j], x1i = pi[j];
                pr[i] = u00r * x0r - u00i * x0i + u01r * x1r - u01i * x1i;
                pi[i] = u00r * x0i + u00i * x0r + u01r * x1i + u01i * x1r;
                pr[j] = u10r * x0r - u10i * x0i + u11r * x1r - u11i * x1i;
                pi[j] = u10r * x0i + u10i * x0r + u11r * x1i + u11i * x1r;
            }
        }
    }

    float e0 = 0.f, e1 = 0.f, e2 = 0.f, e3 = 0.f;
    #pragma unroll
    for (int i = 0; i < 16; ++i) {
        float pp = pr[i] * pr[i] + pi[i] * pi[i];
        e0 += (i & 8) ? -pp : pp;
        e1 += (i & 4) ? -pp : pp;
        e2 += (i & 2) ? -pp : pp;
        e3 += (i & 1) ? -pp : pp;
    }

    ez[t] = make_float4(e0, e1, e2, e3);
    __syncthreads();

    // ---------------- coalesced FC epilogue ----------------
    const int lane = t & 31;
    const int wi   = t >> 5;
    const float4* fw4 = (const float4*)fcw;
    float4 wr0 = fw4[4 * lane + 0];
    float4 wr1 = fw4[4 * lane + 1];
    float4 wr2 = fw4[4 * lane + 2];
    float4 wr3 = fw4[4 * lane + 3];
    float4 bb4 = ((const float4*)fcb)[lane];

    float4* ob = (float4*)out + (size_t)b * 4096 * 32;
    #pragma unroll 4
    for (int j = 0; j < 32; ++j) {
        const int lp = wi * 32 + j;
        float4 e = ez[lp];
        const int py = h0 + (lp >> 4);
        const int px = w0 + (lp & 15);
        const int p  = py * WW + px;
        float4 o;
        o.x = bb4.x + wr0.x * e.x + wr0.y * e.y + wr0.z * e.z + wr0.w * e.w;
        o.y = bb4.y + wr1.x * e.x + wr1.y * e.y + wr1.z * e.z + wr1.w * e.w;
        o.z = bb4.z + wr2.x * e.x + wr2.y * e.y + wr2.z * e.z + wr2.w * e.w;
        o.w = bb4.w + wr3.x * e.x + wr3.y * e.y + wr3.z * e.z + wr3.w * e.w;
        ob[(size_t)p * 32 + lane] = o;
    }
}

extern "C" void kernel_launch(void* const* d_in, const int* in_sizes, int n_in,
                              void* d_out, int out_size)
{
    (void)in_sizes; (void)n_in; (void)out_size;
    const float* x    = (const float*)d_in[0];
    const float* fc1w = (const float*)d_in[1];
    const float* fc1b = (const float*)d_in[2];
    const float* u3p  = (const float*)d_in[3];
    const float* cu3p = (const float*)d_in[4];
    const float* fcw  = (const float*)d_in[5];
    const float* fcb  = (const float*)d_in[6];
    float* out = (float*)d_out;

    init_gates_kernel<<<1, 32>>>(u3p, cu3p);
    dim3 grid(WW / TW, HH / TH, 16);
    qconv_kernel<<<grid, NTHR>>>(x, fc1w, fc1b, fcw, fcb, out);
}